// round 5
// baseline (speedup 1.0000x reference)
#include <cuda_runtime.h>

#define GRID1  592          // 148 SMs * 4 CTAs -> exactly one resident wave
#define BLOCK1 256
#define BATCH  4

__device__ float        g_partials[GRID1 * 8];
__device__ unsigned int g_ticket;   // zero-init; last block resets each launch

struct Acc {
    float sm[4];
    unsigned cntp;
};

// One float4-group = 2 complex elements: x4 = (re0, im0, re1, im1), d2 = (d0, d1)
__device__ __forceinline__ void process2(Acc& A, const float2& d2,
                                         const float4& xv, const float4& yv)
{
    float ds[2] = {d2.x, d2.y};
    float e0[2] = {xv.x, xv.z};
    float e1[2] = {xv.y, xv.w};
    float f0[2] = {yv.x, yv.z};
    float f1[2] = {yv.y, yv.w};

    #pragma unroll
    for (int e = 0; e < 2; e++) {
        float a = e0[e], b = e1[e], c = f0[e], d = f1[e];
        float u  = a - c;
        float v  = b - d;
        float d2s = fmaf(u, u, v * v);
        // (|x|-|y|)^2 = x2 + y2 - 2*sqrt(x2*y2): one MUFU per element
        float x2 = fmaf(a, a, b * b);
        float y2 = fmaf(c, c, d * d);
        float p  = fmaxf(x2 * y2, 1e-30f);
        float s  = p * rsqrtf(p);
        float a2 = x2 + y2 - 2.0f * s;
        float m  = fmaf(0.2f, a2, d2s);
        int ib = (int)(ds[e] * 4.0f);
        ib = ib > 3 ? 3 : ib;
        A.cntp += 1u << (ib << 3);
        #pragma unroll
        for (int bb = 0; bb < 4; bb++)
            if (bb == ib) A.sm[bb] += m;
    }
}

__global__ __launch_bounds__(BLOCK1, 4)
void radial_fused(const float4* __restrict__ x4,
                  const float4* __restrict__ y4,
                  const float2* __restrict__ d2,
                  int m,                 // number of float4-groups = n/2
                  const float* __restrict__ x,
                  const float* __restrict__ y,
                  const float* __restrict__ dist,
                  int n,
                  float* __restrict__ out)
{
    Acc A;
    A.sm[0] = A.sm[1] = A.sm[2] = A.sm[3] = 0.f;
    A.cntp = 0u;

    const int stride = gridDim.x * blockDim.x;
    int i = blockIdx.x * blockDim.x + threadIdx.x;

    // Batched main loop: 12 independent, fully-coalesced loads per iteration.
    for (; i + (BATCH - 1) * stride < m; i += BATCH * stride) {
        float4 xs[BATCH], ys[BATCH];
        float2 dsv[BATCH];
        #pragma unroll
        for (int u = 0; u < BATCH; u++) {
            int k = i + u * stride;
            xs[u]  = __ldcs(x4 + k);
            ys[u]  = __ldcs(y4 + k);
            dsv[u] = __ldcs(d2 + k);
        }
        #pragma unroll
        for (int u = 0; u < BATCH; u++)
            process2(A, dsv[u], xs[u], ys[u]);
    }
    // Epilogue: remaining units one at a time.
    for (; i < m; i += stride) {
        float4 xv = __ldcs(x4 + i);
        float4 yv = __ldcs(y4 + i);
        float2 dv = __ldcs(d2 + i);
        process2(A, dv, xv, yv);
    }

    // Scalar tail (n odd) — no-op at this problem size.
    if (blockIdx.x == 0 && threadIdx.x == 0) {
        for (int jj = m * 2; jj < n; jj++) {
            float a = x[2 * jj], b = x[2 * jj + 1];
            float c = y[2 * jj], d = y[2 * jj + 1];
            float u  = a - c, v = b - d;
            float d2s = fmaf(u, u, v * v);
            float x2 = fmaf(a, a, b * b);
            float y2 = fmaf(c, c, d * d);
            float p  = fmaxf(x2 * y2, 1e-30f);
            float s  = p * rsqrtf(p);
            float a2 = x2 + y2 - 2.0f * s;
            float mm = fmaf(0.2f, a2, d2s);
            int ib = (int)(dist[jj] * 4.0f);
            ib = ib > 3 ? 3 : ib;
            A.sm[ib] += mm;
            A.cntp += 1u << (ib << 3);
        }
    }

    // Block reduction of 8 values in fixed order (deterministic).
    float v[8];
    #pragma unroll
    for (int b = 0; b < 4; b++) {
        v[b]     = A.sm[b];
        v[4 + b] = (float)((A.cntp >> (b << 3)) & 0xFFu);
    }

    __shared__ float sh[BLOCK1 / 32][8];
    const int lane = threadIdx.x & 31;
    const int wid  = threadIdx.x >> 5;

    #pragma unroll
    for (int k = 0; k < 8; k++) {
        #pragma unroll
        for (int o = 16; o > 0; o >>= 1)
            v[k] += __shfl_down_sync(0xffffffffu, v[k], o);
    }
    if (lane == 0) {
        #pragma unroll
        for (int k = 0; k < 8; k++) sh[wid][k] = v[k];
    }
    __syncthreads();
    if (threadIdx.x < 8) {
        float s = 0.f;
        #pragma unroll
        for (int w = 0; w < BLOCK1 / 32; w++) s += sh[w][threadIdx.x];
        g_partials[blockIdx.x * 8 + threadIdx.x] = s;
    }

    // ---- last-block final reduction (threadfence + ticket) ----
    __shared__ int isLast;
    __threadfence();
    if (threadIdx.x == 0) {
        unsigned t = atomicAdd(&g_ticket, 1u);
        isLast = (t == (unsigned)(gridDim.x - 1));
    }
    __syncthreads();
    if (!isLast) return;

    const int k  = threadIdx.x & 7;
    const int r0 = threadIdx.x >> 3;
    float acc = 0.f;
    for (int r = r0; r < GRID1; r += 32)          // fixed order per thread
        acc += g_partials[r * 8 + k];

    __shared__ float sh2[256];
    __shared__ float fin[8];
    sh2[threadIdx.x] = acc;
    __syncthreads();
    if (threadIdx.x < 8) {
        float s = 0.f;
        #pragma unroll
        for (int jj = 0; jj < 32; jj++) s += sh2[jj * 8 + threadIdx.x];
        fin[threadIdx.x] = s;
    }
    __syncthreads();

    if (threadIdx.x == 0) {
        float loss = 0.f;
        #pragma unroll
        for (int b = 0; b < 4; b++) {
            float c = fin[4 + b];
            if (c > 0.f) loss += fin[b] / (2.0f * c);
        }
        out[0] = loss;
        g_ticket = 0u;   // reset for next graph replay
    }
}

extern "C" void kernel_launch(void* const* d_in, const int* in_sizes, int n_in,
                              void* d_out, int out_size)
{
    const float* x    = (const float*)d_in[0];   // [N,2] f32
    const float* y    = (const float*)d_in[1];   // [N,2] f32
    const float* dist = (const float*)d_in[2];   // [N]   f32
    const int n = in_sizes[2];
    const int m = n >> 1;                        // float4-groups (2 elements each)

    radial_fused<<<GRID1, BLOCK1>>>(
        (const float4*)x, (const float4*)y, (const float2*)dist,
        m, x, y, dist, n, (float*)d_out);
}

// round 6
// speedup vs baseline: 1.0453x; 1.0453x over previous
#include <cuda_runtime.h>

#define GRID1  592          // 148 SMs * 4 CTAs -> exactly one resident wave
#define BLOCK1 256

__device__ float        g_partials[GRID1 * 8];
__device__ unsigned int g_ticket;   // zero-init; last block resets each launch

struct Acc {
    float sm[4];
    unsigned cntp;
};

__device__ __forceinline__ void process4(Acc& A, const float4& dd,
                                         const float4& xa, const float4& xb,
                                         const float4& ya, const float4& yb)
{
    float ds[4] = {dd.x, dd.y, dd.z, dd.w};
    float e0[4] = {xa.x, xa.z, xb.x, xb.z};
    float e1[4] = {xa.y, xa.w, xb.y, xb.w};
    float f0[4] = {ya.x, ya.z, yb.x, yb.z};
    float f1[4] = {ya.y, ya.w, yb.y, yb.w};

    #pragma unroll
    for (int e = 0; e < 4; e++) {
        float a = e0[e], b = e1[e], c = f0[e], d = f1[e];
        float u  = a - c;
        float v  = b - d;
        float d2 = fmaf(u, u, v * v);
        // (|x|-|y|)^2 = x2 + y2 - 2*sqrt(x2*y2): one MUFU per element
        float x2 = fmaf(a, a, b * b);
        float y2 = fmaf(c, c, d * d);
        float p  = fmaxf(x2 * y2, 1e-30f);
        float s  = p * rsqrtf(p);
        float a2 = x2 + y2 - 2.0f * s;
        float m  = fmaf(0.2f, a2, d2);
        int ib = (int)(ds[e] * 4.0f);
        ib = ib > 3 ? 3 : ib;
        A.cntp += 1u << (ib << 3);
        #pragma unroll
        for (int bb = 0; bb < 4; bb++)
            if (bb == ib) A.sm[bb] += m;
    }
}

#define LOAD_UNIT(D, XA, XB, YA, YB, idx)          \
    do {                                           \
        D  = __ldcs(d4 + (idx));                   \
        XA = __ldcs(x4 + 2 * (idx) + 0);           \
        XB = __ldcs(x4 + 2 * (idx) + 1);           \
        YA = __ldcs(y4 + 2 * (idx) + 0);           \
        YB = __ldcs(y4 + 2 * (idx) + 1);           \
    } while (0)

__global__ __launch_bounds__(BLOCK1, 4)
void radial_fused(const float4* __restrict__ x4,
                  const float4* __restrict__ y4,
                  const float4* __restrict__ d4,
                  int nvec,
                  const float* __restrict__ x,
                  const float* __restrict__ y,
                  const float* __restrict__ dist,
                  int n,
                  float* __restrict__ out)
{
    Acc A;
    A.sm[0] = A.sm[1] = A.sm[2] = A.sm[3] = 0.f;
    A.cntp = 0u;

    const int stride = gridDim.x * blockDim.x;
    int i = blockIdx.x * blockDim.x + threadIdx.x;

    // Two-stage software pipeline: while processing unit A, unit B's 5
    // LDG.128 are already in flight (and vice versa). A warp always has
    // >=5 independent loads outstanding during compute.
    float4 dA, xa0, xa1, ya0, ya1;
    float4 dB, xb0, xb1, yb0, yb1;

    if (i < nvec) LOAD_UNIT(dA, xa0, xa1, ya0, ya1, i);
    int j = i + stride;
    while (j < nvec) {
        LOAD_UNIT(dB, xb0, xb1, yb0, yb1, j);
        process4(A, dA, xa0, xa1, ya0, ya1);
        i = j + stride;
        if (i < nvec) LOAD_UNIT(dA, xa0, xa1, ya0, ya1, i);
        process4(A, dB, xb0, xb1, yb0, yb1);
        j = i + stride;
    }
    if (i < nvec)
        process4(A, dA, xa0, xa1, ya0, ya1);

    // Scalar tail (n % 4 != 0) — no-op at this problem size.
    if (blockIdx.x == 0 && threadIdx.x == 0) {
        for (int jj = nvec * 4; jj < n; jj++) {
            float a = x[2 * jj], b = x[2 * jj + 1];
            float c = y[2 * jj], d = y[2 * jj + 1];
            float u  = a - c, v = b - d;
            float d2 = fmaf(u, u, v * v);
            float x2 = fmaf(a, a, b * b);
            float y2 = fmaf(c, c, d * d);
            float p  = fmaxf(x2 * y2, 1e-30f);
            float s  = p * rsqrtf(p);
            float a2 = x2 + y2 - 2.0f * s;
            float m  = fmaf(0.2f, a2, d2);
            int ib = (int)(dist[jj] * 4.0f);
            ib = ib > 3 ? 3 : ib;
            A.sm[ib] += m;
            A.cntp += 1u << (ib << 3);
        }
    }

    // Block reduction of 8 values in fixed order (deterministic).
    float v[8];
    #pragma unroll
    for (int b = 0; b < 4; b++) {
        v[b]     = A.sm[b];
        v[4 + b] = (float)((A.cntp >> (b << 3)) & 0xFFu);
    }

    __shared__ float sh[BLOCK1 / 32][8];
    const int lane = threadIdx.x & 31;
    const int wid  = threadIdx.x >> 5;

    #pragma unroll
    for (int k = 0; k < 8; k++) {
        #pragma unroll
        for (int o = 16; o > 0; o >>= 1)
            v[k] += __shfl_down_sync(0xffffffffu, v[k], o);
    }
    if (lane == 0) {
        #pragma unroll
        for (int k = 0; k < 8; k++) sh[wid][k] = v[k];
    }
    __syncthreads();
    if (threadIdx.x < 8) {
        float s = 0.f;
        #pragma unroll
        for (int w = 0; w < BLOCK1 / 32; w++) s += sh[w][threadIdx.x];
        g_partials[blockIdx.x * 8 + threadIdx.x] = s;
    }

    // ---- last-block final reduction (threadfence + ticket) ----
    __shared__ int isLast;
    __threadfence();
    if (threadIdx.x == 0) {
        unsigned t = atomicAdd(&g_ticket, 1u);
        isLast = (t == (unsigned)(gridDim.x - 1));
    }
    __syncthreads();
    if (!isLast) return;

    const int k  = threadIdx.x & 7;
    const int r0 = threadIdx.x >> 3;
    float acc = 0.f;
    for (int r = r0; r < GRID1; r += 32)          // fixed order per thread
        acc += g_partials[r * 8 + k];

    __shared__ float sh2[256];
    __shared__ float fin[8];
    sh2[threadIdx.x] = acc;
    __syncthreads();
    if (threadIdx.x < 8) {
        float s = 0.f;
        #pragma unroll
        for (int jj = 0; jj < 32; jj++) s += sh2[jj * 8 + threadIdx.x];
        fin[threadIdx.x] = s;
    }
    __syncthreads();

    if (threadIdx.x == 0) {
        float loss = 0.f;
        #pragma unroll
        for (int b = 0; b < 4; b++) {
            float c = fin[4 + b];
            if (c > 0.f) loss += fin[b] / (2.0f * c);
        }
        out[0] = loss;
        g_ticket = 0u;   // reset for next graph replay
    }
}

extern "C" void kernel_launch(void* const* d_in, const int* in_sizes, int n_in,
                              void* d_out, int out_size)
{
    const float* x    = (const float*)d_in[0];   // [N,2] f32
    const float* y    = (const float*)d_in[1];   // [N,2] f32
    const float* dist = (const float*)d_in[2];   // [N]   f32
    const int n    = in_sizes[2];
    const int nvec = n >> 2;

    radial_fused<<<GRID1, BLOCK1>>>(
        (const float4*)x, (const float4*)y, (const float4*)dist,
        nvec, x, y, dist, n, (float*)d_out);
}